// round 4
// baseline (speedup 1.0000x reference)
#include <cuda_runtime.h>
#include <cstdint>

#define N_TOK 131072
#define DIM   64
#define QSTG  8
#define KCB   1024

#define TM       128              // tokens per CTA
#define TKC      256              // codewords per chunk
#define NCHUNKS  32               // 8 stages * 4 chunks
#define NTHREADS 256

typedef unsigned long long ull;
typedef unsigned int uint;

// ---- dynamic smem layout (floats) ----
// sB[2] : 64 rows x 258 floats (1032B rows; row d holds 128 k-pairs
//         (B[2p][d],B[2p+1][d]) at 8B slot (p ^ (d>>2)))
// sA    : [TM][DIM] raw residual tile
// redV/redI : [TM][16]
#define SB_ROWF  258
#define BUF_F    (64 * SB_ROWF)            // 16512 floats per buffer
#define SA_OFF   (2 * BUF_F)               // 33024
#define REDV_OFF (SA_OFF + TM * DIM)       // 33024 + 8192
#define REDI_OFF (REDV_OFF + TM * 16)
#define SMEM_FLOATS (REDI_OFF + TM * 16)
#define SMEM_BYTES  (SMEM_FLOATS * 4)      // 181248 B

__device__ double g_loss[QSTG];
__device__ float  g_cnorm[QSTG * KCB];

__device__ __forceinline__ void ffma2(ull& d, ull a, ull b) {
    asm("fma.rn.f32x2 %0, %1, %2, %0;" : "+l"(d) : "l"(a), "l"(b));
}
__device__ __forceinline__ ull dup2(float a) {
    ull r; unsigned u = __float_as_uint(a);
    asm("mov.b64 %0, {%1, %1};" : "=l"(r) : "r"(u));
    return r;
}
__device__ __forceinline__ float2 unpack2(ull v) {
    float2 r;
    asm("mov.b64 {%0, %1}, %2;" : "=f"(r.x), "=f"(r.y) : "l"(v));
    return r;
}
__device__ __forceinline__ void cp_async4(uint dst, const void* src) {
    asm volatile("cp.async.ca.shared.global [%0], [%1], 4;" :: "r"(dst), "l"(src));
}
__device__ __forceinline__ void cp_commit() {
    asm volatile("cp.async.commit_group;");
}
template <int N>
__device__ __forceinline__ void cp_wait() {
    asm volatile("cp.async.wait_group %0;" :: "n"(N));
}

// ---------------------------------------------------------------------------
__global__ void prep_kernel(const float* __restrict__ cb) {
    int k = blockIdx.x * blockDim.x + threadIdx.x;
    if (k < QSTG * KCB) {
        const float* p = cb + (size_t)k * DIM;
        float s0 = 0.f, s1 = 0.f, s2 = 0.f, s3 = 0.f;
#pragma unroll
        for (int d = 0; d < DIM; d += 4) {
            s0 = __fadd_rn(s0, __fmul_rn(p[d + 0], p[d + 0]));
            s1 = __fadd_rn(s1, __fmul_rn(p[d + 1], p[d + 1]));
            s2 = __fadd_rn(s2, __fmul_rn(p[d + 2], p[d + 2]));
            s3 = __fadd_rn(s3, __fmul_rn(p[d + 3], p[d + 3]));
        }
        g_cnorm[k] = __fadd_rn(__fadd_rn(s0, s1), __fadd_rn(s2, s3));
    }
    if (blockIdx.x == 0 && threadIdx.x < QSTG) g_loss[threadIdx.x] = 0.0;
}

// ---------------------------------------------------------------------------
// staging: scatter chunk c of the codebook into transposed-pair layout.
// element B[k][d] -> buf row d (1032B), 8B slot ((k>>1) ^ (d>>2)), half (k&1).
// per thread: d fixed, k = k0 + 4s (coalesced 128B global reads).
// ---------------------------------------------------------------------------
__device__ __forceinline__ void prefetch_chunk(uint buf_base, const float* cbq_chunk,
                                               int tid) {
    const int d   = tid & 63;
    const int k0  = tid >> 6;          // 0..3
    const int dq  = d >> 2;
    const int p0  = k0 >> 1;           // 0 or 1
    const uint rowb = buf_base + (uint)d * (SB_ROWF * 4) + 4u * (uint)(k0 & 1);
    const float* src = cbq_chunk + (size_t)k0 * DIM + d;
#pragma unroll
    for (int s = 0; s < 64; ++s) {
        uint slot = (uint)((p0 + 2 * s) ^ dq);
        cp_async4(rowb + 8u * slot, src + (size_t)s * 256);
    }
    cp_commit();
}

// ---------------------------------------------------------------------------
// fused 8-stage VQ: residual tile in SMEM, B double-buffered via cp.async
// ---------------------------------------------------------------------------
__global__ void __launch_bounds__(NTHREADS, 1)
vq_kernel(const float* __restrict__ x, const float* __restrict__ cb,
          float* __restrict__ out) {
    extern __shared__ float sm[];
    float* sA   = sm + SA_OFF;
    float* redV = sm + REDV_OFF;
    int*   redI = (int*)(sm + REDI_OFF);
    __shared__ int   finIdx[TM];
    __shared__ float wsum[NTHREADS / 32];

    const int tid  = threadIdx.x;
    const int tokg = tid >> 4;    // 0..15 : 8 tokens each
    const int cwg  = tid & 15;    // 0..15 : 8 k-pairs each (p = cwg + 16j)
    const int n0   = blockIdx.x * TM;

    const uint smem_base = (uint)__cvta_generic_to_shared((void*)sm);

    float* out_xq  = out;
    float* out_idx = out + (size_t)N_TOK * DIM;

    // ---- load token tile (raw, coalesced) ----
    {
        const float4* gin = (const float4*)(x + (size_t)n0 * DIM);
        float4* sA4 = (float4*)sA;
#pragma unroll
        for (int i = tid; i < TM * DIM / 4; i += NTHREADS) sA4[i] = gin[i];
    }

    // ---- prefetch chunks 0, 1 ----
    prefetch_chunk(smem_base, cb, tid);
    prefetch_chunk(smem_base + BUF_F * 4, cb + (size_t)TKC * DIM, tid);

    for (int q = 0; q < QSTG; ++q) {
        float bestv[8];
        int   besti[8];
#pragma unroll
        for (int i = 0; i < 8; ++i) { bestv[i] = 3.4e38f; besti[i] = 0; }

        for (int ch = 0; ch < 4; ++ch) {
            const int c = q * 4 + ch;
            const float* sB = sm + (c & 1) * BUF_F;

            if (c == NCHUNKS - 1) cp_wait<0>(); else cp_wait<1>();
            __syncthreads();   // chunk c resident; sA writers done

            // ---- mainloop: 8 tokens x 8 k-pairs per thread ----
            ull acc[64];
#pragma unroll
            for (int i = 0; i < 64; ++i) acc[i] = 0ull;

            const float* aTok = sA + tokg * 8 * DIM;
#pragma unroll 4
            for (int d = 0; d < DIM; ++d) {
                ull a2[8];
#pragma unroll
                for (int ti = 0; ti < 8; ++ti)
                    a2[ti] = dup2(aTok[ti * DIM + d]);
                const ull* bRow = (const ull*)(sB + d * SB_ROWF) + (cwg ^ (d >> 2));
                ull b2[8];
#pragma unroll
                for (int j = 0; j < 8; ++j) b2[j] = bRow[16 * j];
#pragma unroll
                for (int ti = 0; ti < 8; ++ti)
#pragma unroll
                    for (int j = 0; j < 8; ++j)
                        ffma2(acc[ti * 8 + j], a2[ti], b2[j]);
            }
            __syncthreads();   // all reads of buffer (c&1) complete

            // ---- prefetch chunk c+2 into freed buffer (overlaps epilogue) ----
            if (c + 2 < NCHUNKS)
                prefetch_chunk(smem_base + (c & 1) * (BUF_F * 4),
                               cb + (size_t)(c + 2) * TKC * DIM, tid);

            // ---- running argmin: val = cnorm - 2*dot (k-pair fold) ----
#pragma unroll
            for (int j = 0; j < 8; ++j) {
                const int kl = 2 * (cwg + 16 * j);          // stage-local, within chunk
                const int kg = ch * TKC + kl;
                const float2 cn = __ldg((const float2*)&g_cnorm[q * KCB + kg]);
#pragma unroll
                for (int ti = 0; ti < 8; ++ti) {
                    float2 p = unpack2(acc[ti * 8 + j]);
                    float v0 = fmaf(-2.0f, p.x, cn.x);
                    float v1 = fmaf(-2.0f, p.y, cn.y);
                    bool l0 = v0 < bestv[ti];
                    bestv[ti] = l0 ? v0 : bestv[ti];
                    besti[ti] = l0 ? kg : besti[ti];
                    bool l1 = v1 < bestv[ti];
                    bestv[ti] = l1 ? v1 : bestv[ti];
                    besti[ti] = l1 ? (kg + 1) : besti[ti];
                }
            }
        }
        __syncthreads();

        // ---- cross-thread argmin (16 partials per token) ----
#pragma unroll
        for (int ti = 0; ti < 8; ++ti) {
            int t = tokg * 8 + ti;
            redV[t * 16 + cwg] = bestv[ti];
            redI[t * 16 + cwg] = besti[ti];
        }
        __syncthreads();
        if (tid < TM) {
            const float* rv = redV + tid * 16;
            const int*   ri = redI + tid * 16;
            float bv = rv[0];
            int   bi = ri[0];
#pragma unroll
            for (int g = 1; g < 16; ++g) {
                float v  = rv[g];
                int   ii = ri[g];
                if (v < bv || (v == bv && ii < bi)) { bv = v; bi = ii; }
            }
            finIdx[tid] = bi;
            out_idx[(size_t)(n0 + tid) * QSTG + q] = (float)bi;
        }
        __syncthreads();

        // ---- residual update (in sA) + commitment loss ----
        {
            const int t = tid >> 1, hd = tid & 1;
            const int idx = finIdx[t];
            const float4* c4 =
                (const float4*)(cb + (size_t)q * KCB * DIM + (size_t)idx * DIM + hd * 32);
            float4* r4 = (float4*)(sA + t * DIM + hd * 32);
            float ls = 0.f;
#pragma unroll
            for (int m = 0; m < 8; ++m) {
                float4 rv = r4[m], cv = c4[m], nv;
                nv.x = __fsub_rn(rv.x, cv.x);
                nv.y = __fsub_rn(rv.y, cv.y);
                nv.z = __fsub_rn(rv.z, cv.z);
                nv.w = __fsub_rn(rv.w, cv.w);
                r4[m] = nv;
                ls = fmaf(nv.x, nv.x, ls);
                ls = fmaf(nv.y, nv.y, ls);
                ls = fmaf(nv.z, nv.z, ls);
                ls = fmaf(nv.w, nv.w, ls);
            }
#pragma unroll
            for (int off = 16; off; off >>= 1)
                ls += __shfl_down_sync(0xffffffff, ls, off);
            if ((tid & 31) == 0) wsum[tid >> 5] = ls;
            __syncthreads();
            if (tid == 0) {
                float tot = 0.f;
#pragma unroll
                for (int w = 0; w < NTHREADS / 32; ++w) tot += wsum[w];
                atomicAdd(&g_loss[q], (double)tot);
            }
        }
        // next iteration's top-of-loop __syncthreads orders sA writes vs reads
    }
    __syncthreads();

    // ---- xq = x - final_residual ----
    {
        const float4* x4 = (const float4*)(x + (size_t)n0 * DIM);
        const float4* r4 = (const float4*)sA;
        float4* o4 = (float4*)(out_xq + (size_t)n0 * DIM);
#pragma unroll
        for (int i = tid; i < TM * DIM / 4; i += NTHREADS) {
            float4 xv = x4[i], rv = r4[i], ov;
            ov.x = __fsub_rn(xv.x, rv.x);
            ov.y = __fsub_rn(xv.y, rv.y);
            ov.z = __fsub_rn(xv.z, rv.z);
            ov.w = __fsub_rn(xv.w, rv.w);
            o4[i] = ov;
        }
    }
}

// ---------------------------------------------------------------------------
__global__ void loss_kernel(float* __restrict__ out) {
    if (threadIdx.x < QSTG)
        out[(size_t)N_TOK * DIM + (size_t)N_TOK * QSTG + threadIdx.x] =
            (float)(g_loss[threadIdx.x] / (double)((size_t)N_TOK * DIM));
}

extern "C" void kernel_launch(void* const* d_in, const int* in_sizes, int n_in,
                              void* d_out, int out_size) {
    const float* x  = (const float*)d_in[0];
    const float* cb = (const float*)d_in[1];
    if (n_in >= 2 && in_sizes[0] == QSTG * KCB * DIM && in_sizes[1] == N_TOK * DIM) {
        const float* t = x; x = cb; cb = t;
    }
    float* out = (float*)d_out;

    cudaFuncSetAttribute(vq_kernel,
                         cudaFuncAttributeMaxDynamicSharedMemorySize, SMEM_BYTES);

    prep_kernel<<<(QSTG * KCB + 255) / 256, 256>>>(cb);
    vq_kernel<<<N_TOK / TM, NTHREADS, SMEM_BYTES>>>(x, cb, out);
    loss_kernel<<<1, 32>>>(out);
}